// round 9
// baseline (speedup 1.0000x reference)
#include <cuda_runtime.h>

#define HH 256
#define WW 256
#define BATCH 8
#define HW 65536

typedef unsigned long long ull;

// Scratch (allocation-free rule: __device__ globals)
__device__ float g_x[BATCH * 16 * HW];          // in_conv output  (33.5 MB)

// ---------------- packed f32x2 helpers (sm_100+) ----------------
__device__ __forceinline__ ull pk2(float lo, float hi) {
    ull r;
    asm("mov.b64 %0, {%1, %2};" : "=l"(r) : "r"(__float_as_uint(lo)), "r"(__float_as_uint(hi)));
    return r;
}
__device__ __forceinline__ ull fma2(ull a, ull b, ull c) {
    ull d; asm("fma.rn.f32x2 %0, %1, %2, %3;" : "=l"(d) : "l"(a), "l"(b), "l"(c)); return d;
}

// ---------------------------------------------------------------------------
// K1: 1x1 in_conv 64 -> 16, packed f32x2 FFMA2 (2 px / thread)  [proven]
// ---------------------------------------------------------------------------
__global__ __launch_bounds__(256, 3) void k_inconv(const ull* __restrict__ cen2,
                                                   const float* __restrict__ w,
                                                   const float* __restrict__ bias) {
    __shared__ ull sw[1024];     // {w,w} packed
    __shared__ ull sb[16];
    for (int i = threadIdx.x; i < 1024; i += 256) { float v = w[i]; sw[i] = pk2(v, v); }
    if (threadIdx.x < 16) { float v = bias[threadIdx.x]; sb[threadIdx.x] = pk2(v, v); }
    __syncthreads();

    int idx = blockIdx.x * 256 + threadIdx.x;   // 0 .. 262143  (b, p2)
    int b = idx >> 15;
    int p2 = idx & 32767;
    const ull* cp = cen2 + (size_t)(b * 64) * 32768 + p2;

    ull acc[16];
#pragma unroll
    for (int o = 0; o < 16; o++) acc[o] = sb[o];

#pragma unroll 8
    for (int i = 0; i < 64; i++) {
        ull v = __ldg(cp + (size_t)i * 32768);
#pragma unroll
        for (int o = 0; o < 16; o++) acc[o] = fma2(v, sw[o * 64 + i], acc[o]);
    }
    ull* xp = reinterpret_cast<ull*>(g_x) + (size_t)(b * 16) * 32768 + p2;
#pragma unroll
    for (int o = 0; o < 16; o++) xp[(size_t)o * 32768] = acc[o];
}

// ---------------------------------------------------------------------------
// K2 (fused): dwconv (recomputed with halo) + shifts + grouped mixes + sort8 +
// contraction + sort4 + base conv + SiLU + final 1x1 + sigmoid.
// Tile 32x32, 512 threads, 2 px / thread in the branch phase.
// ---------------------------------------------------------------------------
#define ATILE_N (52 * 56)          // g_x staging, halo 10, row stride 56
#define RB1 2912                   // 34x34 = 1156
#define RB3 4068                   // 38x38 = 1444
#define RB5 5512                   // 42x42 = 1764
#define RB7 7276                   // 46x46 = 2116
#define POOL_N 9392

__device__ __forceinline__ void ce(float& a, float& b) {
    float lo = fminf(a, b);
    float hi = fmaxf(a, b);
    a = lo; b = hi;
}

__device__ __forceinline__ void sort8(float v[8]) {
    ce(v[0], v[1]); ce(v[2], v[3]); ce(v[0], v[2]); ce(v[1], v[3]); ce(v[1], v[2]);
    ce(v[4], v[5]); ce(v[6], v[7]); ce(v[4], v[6]); ce(v[5], v[7]); ce(v[5], v[6]);
    ce(v[0], v[4]); ce(v[1], v[5]); ce(v[2], v[6]); ce(v[3], v[7]);
    ce(v[2], v[4]); ce(v[3], v[5]);
    ce(v[1], v[2]); ce(v[3], v[4]); ce(v[5], v[6]);
}

// Staging prefetch/commit (2912 elements, 512 threads -> 6 regs)
__device__ __forceinline__ void a_prefetch(float r[6], const float* __restrict__ src,
                                           int y0, int x0, int tid) {
#pragma unroll
    for (int j = 0; j < 6; j++) {
        int i = tid + j * 512;
        float v = 0.f;
        if (i < ATILE_N) {
            int ar = i / 56, ac = i % 56;
            int gy = y0 - 10 + ar, gx = x0 - 10 + ac;
            if ((unsigned)gy < 256u && (unsigned)gx < 256u)
                v = __ldg(src + gy * 256 + gx);
        }
        r[j] = v;
    }
}

__device__ __forceinline__ void a_commit(const float r[6], float* __restrict__ sA,
                                         int tid) {
#pragma unroll
    for (int j = 0; j < 6; j++) {
        int i = tid + j * 512;
        if (i < ATILE_N) sA[i] = r[j];
    }
}

// One 4-wide run of depthwise conv S x S.
// Region (RW x RW) at pool[RBASE]; sA tap row offset AOFS (= 10 - S - S/2).
template <int S, int RW, int RBASE, int AOFS>
__device__ __forceinline__ void dw_run(float* __restrict__ pool,
                                       const float* __restrict__ sA,
                                       int row, int cs,
                                       const float* __restrict__ wk, float bias,
                                       int y0, int x0) {
    float acc[4] = {bias, bias, bias, bias};
#pragma unroll
    for (int kh = 0; kh < S; kh++) {
        const float* arow = sA + (row + AOFS + kh) * 56 + cs + AOFS;
        float v[S + 3];
#pragma unroll
        for (int j = 0; j < S + 3; j++) v[j] = arow[j];
#pragma unroll
        for (int kw = 0; kw < S; kw++) {
            float wv = wk[kh * S + kw];
            acc[0] = fmaf(wv, v[kw + 0], acc[0]);
            acc[1] = fmaf(wv, v[kw + 1], acc[1]);
            acc[2] = fmaf(wv, v[kw + 2], acc[2]);
            acc[3] = fmaf(wv, v[kw + 3], acc[3]);
        }
    }
    int gy = y0 - S + row;
    bool yok = (unsigned)gy < 256u;
#pragma unroll
    for (int q = 0; q < 4; q++) {
        int rx = cs + q;
        if (rx < RW) {
            int gx = x0 - S + rx;
            pool[RBASE + row * RW + rx] = (yok && (unsigned)gx < 256u) ? acc[q] : 0.f;
        }
    }
}

template <int S, int C, int RB>
__device__ __forceinline__ float branch_val(const float* __restrict__ pool, int ty,
                                            int tx, const float* __restrict__ wB) {
    const float* ctr = pool + RB + (ty + S) * C + (tx + S);
    float xc = ctr[0];
    float T[8];
    T[0] = xc - ctr[-S * C - S];
    T[1] = xc - ctr[-S * C];
    T[2] = xc - ctr[-S * C + S];
    T[3] = xc - ctr[S];
    T[4] = xc - ctr[S * C + S];
    T[5] = xc - ctr[S * C];
    T[6] = xc - ctr[S * C - S];
    T[7] = xc - ctr[-S];
    float Sv[4];
#pragma unroll
    for (int k = 0; k < 4; k++) Sv[k] = T[k] + T[k + 4];

    float w10 = wB[0], w11 = wB[1], w12 = wB[2], w13x2 = wB[3], b1 = wB[4];
    float base[4];
#pragma unroll
    for (int j = 0; j < 4; j++) {
        float o = fmaf(w10, Sv[(j + 1) & 3], b1);
        o = fmaf(w11, Sv[(j + 3) & 3], o);
        base[j] = fmaf(w12, Sv[(j + 2) & 3], o);
    }
    float v[8];
#pragma unroll
    for (int k = 0; k < 8; k++)
        v[k] = fmaf(w13x2, T[(k + 4) & 7], base[k & 3]) * T[k];  // wB[3] pre-doubled

    sort8(v);

    float r = wB[13];
#pragma unroll
    for (int j = 0; j < 8; j++) r = fmaf(v[j], wB[5 + j], r);
    return r;
}

__global__ __launch_bounds__(512, 2) void k_fuse(
    const float* __restrict__ w1, const float* __restrict__ b1,
    const float* __restrict__ w3, const float* __restrict__ b3,
    const float* __restrict__ w5, const float* __restrict__ b5,
    const float* __restrict__ w7, const float* __restrict__ b7,
    const float* __restrict__ l1_w, const float* __restrict__ l1_b,
    const float* __restrict__ l2_w, const float* __restrict__ l2_b,
    const float* __restrict__ base_w, const float* __restrict__ bn_scale,
    const float* __restrict__ bn_bias, const float* __restrict__ final_w,
    const float* __restrict__ final_b, float* __restrict__ out) {
    __shared__ float pool[POOL_N];       // [0,2912) sA staging; then 4 dw regions
    __shared__ float sdw[16 * 84];       // dw weights per ch: w1@0, w3@1, w5@10, w7@35
    __shared__ float sdb[64];            // dw biases [c][branch]
    __shared__ float swB[4 * 16 * 14];   // branch wts: w1[4](e3 doubled), b1, w2[8], b2
    __shared__ float sbase[64];
    __shared__ float sbnS[16], sbnB[16], sfw[16];

    float* sA = pool;
    int tid = threadIdx.x;

    for (int i = tid; i < 16;  i += 512) sdw[i * 84] = w1[i];
    for (int i = tid; i < 144; i += 512) sdw[(i / 9)  * 84 + 1  + (i % 9)]  = w3[i];
    for (int i = tid; i < 400; i += 512) sdw[(i / 25) * 84 + 10 + (i % 25)] = w5[i];
    for (int i = tid; i < 784; i += 512) sdw[(i / 49) * 84 + 35 + (i % 49)] = w7[i];
    if (tid < 16) {
        sdb[tid * 4 + 0] = b1[tid]; sdb[tid * 4 + 1] = b3[tid];
        sdb[tid * 4 + 2] = b5[tid]; sdb[tid * 4 + 3] = b7[tid];
    }
    for (int i = tid; i < 896; i += 512) {
        int e = i % 14;
        int rest = i / 14;
        int cc = rest % 16, br = rest / 16;
        float v;
        if (e < 4) { v = l1_w[(br * 16 + cc) * 4 + e]; if (e == 3) v *= 2.f; }
        else if (e == 4) v = l1_b[br * 16 + cc];
        else if (e < 13) v = l2_w[(br * 16 + cc) * 8 + (e - 5)];
        else v = l2_b[br * 16 + cc];
        swB[i] = v;
    }
    if (tid < 64) sbase[tid] = base_w[tid];
    if (tid < 16) { sbnS[tid] = bn_scale[tid]; sbnB[tid] = bn_bias[tid]; sfw[tid] = final_w[tid]; }

    int tx = tid & 15, ty = tid >> 4;    // px (ty, tx) and (ty, tx+16), ty 0..31
    int x0 = blockIdx.x * 32, y0 = blockIdx.y * 32;
    int b = blockIdx.z;
    float fb = __ldg(final_b);
    float acc0 = fb, acc1 = fb;

    const float* xsrc = g_x + (size_t)(b * 16) * HW;

    float rA[6];
    a_prefetch(rA, xsrc, y0, x0, tid);

#pragma unroll 1
    for (int c = 0; c < 16; c++) {
        __syncthreads();                 // prior branch-phase reads done; sA free
        a_commit(rA, sA, tid);
        __syncthreads();
        if (c < 15) a_prefetch(rA, xsrc + (size_t)(c + 1) * HW, y0, x0, tid);

        // --- depthwise conv recompute into pool regions ---
        const float* wcp = sdw + c * 84;
        const float* dbc = sdb + c * 4;
        // s=1: 1156 scalar outputs
        {
            float wv = wcp[0], bv = dbc[0];
#pragma unroll
            for (int j = 0; j < 3; j++) {
                int i = tid + j * 512;
                if (i < 1156) {
                    int ry = i / 34, rx = i % 34;
                    int gy = y0 - 1 + ry, gx = x0 - 1 + rx;
                    float v = fmaf(wv, sA[(ry + 9) * 56 + rx + 9], bv);
                    pool[RB1 + i] = ((unsigned)gy < 256u && (unsigned)gx < 256u) ? v : 0.f;
                }
            }
        }
        // s=3: 38 rows x 10 runs = 380
        if (tid < 380)
            dw_run<3, 38, RB3, 6>(pool, sA, tid / 10, (tid % 10) * 4, wcp + 1, dbc[1], y0, x0);
        // s=5: 42 rows x 11 runs = 462
        if (tid < 462)
            dw_run<5, 42, RB5, 3>(pool, sA, tid / 11, (tid % 11) * 4, wcp + 10, dbc[2], y0, x0);
        // s=7: 46 rows x 12 runs = 552
#pragma unroll
        for (int j = 0; j < 2; j++) {
            int run = tid + j * 512;
            if (run < 552)
                dw_run<7, 46, RB7, 0>(pool, sA, run / 12, (run % 12) * 4, wcp + 35, dbc[3], y0, x0);
        }
        __syncthreads();                 // dw regions visible

        // --- branch phase: 2 px per thread ---
#pragma unroll
        for (int h = 0; h < 2; h++) {
            int px = tx + h * 16;
            float bv0 = branch_val<1, 34, RB1>(pool, ty, px, swB + (0 * 16 + c) * 14);
            float bv1 = branch_val<3, 38, RB3>(pool, ty, px, swB + (1 * 16 + c) * 14);
            float bv2 = branch_val<5, 42, RB5>(pool, ty, px, swB + (2 * 16 + c) * 14);
            float bv3 = branch_val<7, 46, RB7>(pool, ty, px, swB + (3 * 16 + c) * 14);

            ce(bv0, bv1); ce(bv2, bv3); ce(bv0, bv2); ce(bv1, bv3); ce(bv1, bv2);

            float y = bv0 * sbase[c * 4 + 0];
            y = fmaf(bv1, sbase[c * 4 + 1], y);
            y = fmaf(bv2, sbase[c * 4 + 2], y);
            y = fmaf(bv3, sbase[c * 4 + 3], y);
            float t = fmaf(y, sbnS[c], sbnB[c]);
            float si = __fdividef(t, 1.f + __expf(-t));
            if (h == 0) acc0 = fmaf(si, sfw[c], acc0);
            else        acc1 = fmaf(si, sfw[c], acc1);
        }
    }
    size_t obase = (size_t)b * HW + (size_t)(y0 + ty) * 256 + x0;
    out[obase + tx]      = __fdividef(1.f, 1.f + __expf(-acc0));
    out[obase + tx + 16] = __fdividef(1.f, 1.f + __expf(-acc1));
}

// ---------------------------------------------------------------------------
extern "C" void kernel_launch(void* const* d_in, const int* in_sizes, int n_in,
                              void* d_out, int out_size) {
    (void)in_sizes; (void)n_in; (void)out_size;
    const ull* cen = (const ull*)d_in[0];
    // d_in[1] = mas (unused by the reference computation)
    const float* in_w = (const float*)d_in[2];
    const float* in_b = (const float*)d_in[3];

    k_inconv<<<1024, 256>>>(cen, in_w, in_b);

    dim3 g(8, 8, 8);   // W/32, H/32, B
    k_fuse<<<g, 512>>>((const float*)d_in[4],  (const float*)d_in[5],
                       (const float*)d_in[6],  (const float*)d_in[7],
                       (const float*)d_in[8],  (const float*)d_in[9],
                       (const float*)d_in[10], (const float*)d_in[11],
                       (const float*)d_in[12], (const float*)d_in[13],
                       (const float*)d_in[14], (const float*)d_in[15],
                       (const float*)d_in[16], (const float*)d_in[17],
                       (const float*)d_in[18], (const float*)d_in[19],
                       (const float*)d_in[20], (float*)d_out);
}

// round 10
// speedup vs baseline: 1.3286x; 1.3286x over previous
#include <cuda_runtime.h>

#define HH 256
#define WW 256
#define BATCH 8
#define HW 65536

typedef unsigned long long ull;

// Scratch (allocation-free rule: __device__ globals)
__device__ float g_x[BATCH * 16 * HW];          // in_conv output  (33.5 MB)
__device__ float g_xs[4 * BATCH * 16 * HW];     // dwconv outputs  (134 MB)

// ---------------- packed f32x2 helpers (sm_100+) ----------------
__device__ __forceinline__ ull pk2(float lo, float hi) {
    ull r;
    asm("mov.b64 %0, {%1, %2};" : "=l"(r) : "r"(__float_as_uint(lo)), "r"(__float_as_uint(hi)));
    return r;
}
__device__ __forceinline__ ull fma2(ull a, ull b, ull c) {
    ull d; asm("fma.rn.f32x2 %0, %1, %2, %3;" : "=l"(d) : "l"(a), "l"(b), "l"(c)); return d;
}

// ---------------------------------------------------------------------------
// K1: 1x1 in_conv 64 -> 16, packed f32x2 FFMA2 (2 px / thread)  [proven]
// ---------------------------------------------------------------------------
__global__ __launch_bounds__(256, 3) void k_inconv(const ull* __restrict__ cen2,
                                                   const float* __restrict__ w,
                                                   const float* __restrict__ bias) {
    __shared__ ull sw[1024];     // {w,w} packed
    __shared__ ull sb[16];
    for (int i = threadIdx.x; i < 1024; i += 256) { float v = w[i]; sw[i] = pk2(v, v); }
    if (threadIdx.x < 16) { float v = bias[threadIdx.x]; sb[threadIdx.x] = pk2(v, v); }
    __syncthreads();

    int idx = blockIdx.x * 256 + threadIdx.x;   // 0 .. 262143  (b, p2)
    int b = idx >> 15;
    int p2 = idx & 32767;
    const ull* cp = cen2 + (size_t)(b * 64) * 32768 + p2;

    ull acc[16];
#pragma unroll
    for (int o = 0; o < 16; o++) acc[o] = sb[o];

#pragma unroll 8
    for (int i = 0; i < 64; i++) {
        ull v = __ldg(cp + (size_t)i * 32768);
#pragma unroll
        for (int o = 0; o < 16; o++) acc[o] = fma2(v, sw[o * 64 + i], acc[o]);
    }
    ull* xp = reinterpret_cast<ull*>(g_x) + (size_t)(b * 16) * 32768 + p2;
#pragma unroll
    for (int o = 0; o < 16; o++) xp[(size_t)o * 32768] = acc[o];
}

// ---------------------------------------------------------------------------
// K2: all 4 depthwise convs (s = 1,3,5,7), tile 32x16, 2 px per thread,
//     register-prefetch pipeline over channels.  [R4, unchanged]
// ---------------------------------------------------------------------------
template <int S>
__device__ __forceinline__ void dw2(const float* __restrict__ sx, int ty, int c0,
                                    const float* __restrict__ wk, float bias,
                                    float& o0, float& o1) {
    constexpr int P = S / 2;
    float a0 = bias, a1 = bias;
#pragma unroll
    for (int kh = 0; kh < S; kh++) {
        const float* row = sx + (ty + 3 - P + kh) * 39 + (c0 + 3 - P);
        float v[S + 1];
#pragma unroll
        for (int j = 0; j <= S; j++) v[j] = row[j];
#pragma unroll
        for (int kw = 0; kw < S; kw++) {
            float wv = wk[kh * S + kw];
            a0 = fmaf(wv, v[kw], a0);
            a1 = fmaf(wv, v[kw + 1], a1);
        }
    }
    o0 = a0; o1 = a1;
}

__device__ __forceinline__ void dw_prefetch(float r[4], const float* __restrict__ src,
                                            int y0, int x0, int tid) {
#pragma unroll
    for (int j = 0; j < 4; j++) {
        int i = tid + j * 256;
        float v = 0.f;
        if (i < 836) {
            int rr = i / 38, cl = i % 38;
            int gy = y0 - 3 + rr, gx = x0 - 3 + cl;
            if ((unsigned)gy < 256u && (unsigned)gx < 256u)
                v = __ldg(src + gy * 256 + gx);
        }
        r[j] = v;
    }
}

__device__ __forceinline__ void dw_commit(const float r[4], float* __restrict__ sxt,
                                          int tid) {
#pragma unroll
    for (int j = 0; j < 4; j++) {
        int i = tid + j * 256;
        if (i < 836) sxt[(i / 38) * 39 + (i % 38)] = r[j];
    }
}

__global__ __launch_bounds__(256) void k_dw(
    const float* __restrict__ w1, const float* __restrict__ b1,
    const float* __restrict__ w3, const float* __restrict__ b3,
    const float* __restrict__ w5, const float* __restrict__ b5,
    const float* __restrict__ w7, const float* __restrict__ b7) {
    __shared__ float sdw[16 * 84];
    __shared__ float sdb[64];
    __shared__ float sxt[22 * 39];

    int tid = threadIdx.x;
    for (int i = tid; i < 16;  i += 256) sdw[i * 84] = w1[i];
    for (int i = tid; i < 144; i += 256) sdw[(i / 9)  * 84 + 1  + (i % 9)]  = w3[i];
    for (int i = tid; i < 400; i += 256) sdw[(i / 25) * 84 + 10 + (i % 25)] = w5[i];
    for (int i = tid; i < 784; i += 256) sdw[(i / 49) * 84 + 35 + (i % 49)] = w7[i];
    if (tid < 16) {
        sdb[tid * 4 + 0] = b1[tid]; sdb[tid * 4 + 1] = b3[tid];
        sdb[tid * 4 + 2] = b5[tid]; sdb[tid * 4 + 3] = b7[tid];
    }

    int ty = tid >> 4;
    int c0 = (tid & 15) * 2;
    int y0 = blockIdx.y * 16, x0 = blockIdx.x * 32;
    int b = blockIdx.z;
    int h = y0 + ty, wc0 = x0 + c0;

    float rb[4];
    dw_prefetch(rb, g_x + (size_t)(b * 16 + 0) * HW, y0, x0, tid);

#pragma unroll 1
    for (int c = 0; c < 16; c++) {
        __syncthreads();
        dw_commit(rb, sxt, tid);
        __syncthreads();
        if (c < 15)
            dw_prefetch(rb, g_x + (size_t)(b * 16 + c + 1) * HW, y0, x0, tid);

        const float* wcp = sdw + c * 84;
        size_t pix = (size_t)h * 256 + wc0;
        float o0, o1;
        dw2<1>(sxt, ty, c0, wcp + 0,  sdb[c * 4 + 0], o0, o1);
        *reinterpret_cast<float2*>(g_xs + (size_t)((0 * BATCH + b) * 16 + c) * HW + pix) = make_float2(o0, o1);
        dw2<3>(sxt, ty, c0, wcp + 1,  sdb[c * 4 + 1], o0, o1);
        *reinterpret_cast<float2*>(g_xs + (size_t)((1 * BATCH + b) * 16 + c) * HW + pix) = make_float2(o0, o1);
        dw2<5>(sxt, ty, c0, wcp + 10, sdb[c * 4 + 2], o0, o1);
        *reinterpret_cast<float2*>(g_xs + (size_t)((2 * BATCH + b) * 16 + c) * HW + pix) = make_float2(o0, o1);
        dw2<7>(sxt, ty, c0, wcp + 35, sdb[c * 4 + 3], o0, o1);
        *reinterpret_cast<float2*>(g_xs + (size_t)((3 * BATCH + b) * 16 + c) * HW + pix) = make_float2(o0, o1);
    }
}

// ---------------------------------------------------------------------------
// K3: fused tail, tile 32x16, 256 threads, 2 px / thread (y-split: ty, ty+8).
// Scalar math; the two pixels are fully independent -> 2x ILP along the whole
// LDS -> FMA -> sort chain.  Channel register-prefetch pipeline retained.
// ---------------------------------------------------------------------------
__device__ __forceinline__ void ce(float& a, float& b) {
    float lo = fminf(a, b);
    float hi = fmaxf(a, b);
    a = lo; b = hi;
}

__device__ __forceinline__ void sort8(float v[8]) {
    ce(v[0], v[1]); ce(v[2], v[3]); ce(v[0], v[2]); ce(v[1], v[3]); ce(v[1], v[2]);
    ce(v[4], v[5]); ce(v[6], v[7]); ce(v[4], v[6]); ce(v[5], v[7]); ce(v[5], v[6]);
    ce(v[0], v[4]); ce(v[1], v[5]); ce(v[2], v[6]); ce(v[3], v[7]);
    ce(v[2], v[4]); ce(v[3], v[5]);
    ce(v[1], v[2]); ce(v[3], v[4]); ce(v[5], v[6]);
}

// Two independent pixels (ty, tx) and (ty+8, tx) in one pass.
template <int S, int C>
__device__ __forceinline__ void branch_val_2y(const float* __restrict__ sx, int ty,
                                              int tx, const float* __restrict__ wB,
                                              float& ra, float& rb) {
    const float* ctrA = sx + (ty + S) * C + (tx + S);
    const float* ctrB = ctrA + 8 * C;
    float xcA = ctrA[0], xcB = ctrB[0];
    float TA[8], TB[8];
    const int offs[8] = {-S * C - S, -S * C, -S * C + S, S,
                         S * C + S, S * C, S * C - S, -S};
#pragma unroll
    for (int j = 0; j < 8; j++) {
        TA[j] = xcA - ctrA[offs[j]];
        TB[j] = xcB - ctrB[offs[j]];
    }
    float SvA[4], SvB[4];
#pragma unroll
    for (int k = 0; k < 4; k++) { SvA[k] = TA[k] + TA[k + 4]; SvB[k] = TB[k] + TB[k + 4]; }

    float w10 = wB[0], w11 = wB[1], w12 = wB[2], w13x2 = wB[3], b1 = wB[4];
    float baseA[4], baseB[4];
#pragma unroll
    for (int j = 0; j < 4; j++) {
        float oA = fmaf(w10, SvA[(j + 1) & 3], b1);
        float oB = fmaf(w10, SvB[(j + 1) & 3], b1);
        oA = fmaf(w11, SvA[(j + 3) & 3], oA);
        oB = fmaf(w11, SvB[(j + 3) & 3], oB);
        baseA[j] = fmaf(w12, SvA[(j + 2) & 3], oA);
        baseB[j] = fmaf(w12, SvB[(j + 2) & 3], oB);
    }
    float vA[8], vB[8];
#pragma unroll
    for (int k = 0; k < 8; k++) {
        vA[k] = fmaf(w13x2, TA[(k + 4) & 7], baseA[k & 3]) * TA[k];
        vB[k] = fmaf(w13x2, TB[(k + 4) & 7], baseB[k & 3]) * TB[k];
    }
    sort8(vA);
    sort8(vB);
    float aa = wB[13], bb = wB[13];
#pragma unroll
    for (int j = 0; j < 8; j++) {
        float wv = wB[5 + j];
        aa = fmaf(vA[j], wv, aa);
        bb = fmaf(vB[j], wv, bb);
    }
    ra = aa; rb = bb;
}

template <int S, int NR>
__device__ __forceinline__ void m_prefetch(float r[NR], const float* __restrict__ src,
                                           int y0, int x0, int tid) {
    constexpr int R = 16 + 2 * S, C = 32 + 2 * S;
#pragma unroll
    for (int j = 0; j < NR; j++) {
        int i = tid + j * 256;
        float v = 0.f;
        if (i < R * C) {
            int rr = i / C, cl = i % C;
            int gy = y0 - S + rr, gx = x0 - S + cl;
            if ((unsigned)gy < 256u && (unsigned)gx < 256u)
                v = __ldg(src + gy * 256 + gx);
        }
        r[j] = v;
    }
}

template <int S, int NR>
__device__ __forceinline__ void m_commit(const float r[NR], float* __restrict__ dst,
                                         int tid) {
    constexpr int R = 16 + 2 * S, C = 32 + 2 * S;
#pragma unroll
    for (int j = 0; j < NR; j++) {
        int i = tid + j * 256;
        if (i < R * C) dst[i] = r[j];
    }
}

__global__ __launch_bounds__(256) void k_main(
    const float* __restrict__ l1_w, const float* __restrict__ l1_b,
    const float* __restrict__ l2_w, const float* __restrict__ l2_b,
    const float* __restrict__ base_w, const float* __restrict__ bn_scale,
    const float* __restrict__ bn_bias, const float* __restrict__ final_w,
    const float* __restrict__ final_b, float* __restrict__ out) {
    // Regions for 32x16 tile: S=1: 18x34=612 @0; S=3: 22x38=836 @612;
    // S=5: 26x42=1092 @1448; S=7: 30x46=1380 @2540; total 3920
    __shared__ float sxt[3920];
    __shared__ float swB[4 * 16 * 14];   // per branch/channel: w1[4],b1,w2[8],b2
    __shared__ float sbase[64];
    __shared__ float sbnS[16], sbnB[16], sfw[16];

    int tid = threadIdx.x;
    for (int i = tid; i < 896; i += 256) {
        int e = i % 14;
        int rest = i / 14;
        int cc = rest % 16, br = rest / 16;
        float v;
        if (e < 4) { v = l1_w[(br * 16 + cc) * 4 + e]; if (e == 3) v *= 2.f; }
        else if (e == 4) v = l1_b[br * 16 + cc];
        else if (e < 13) v = l2_w[(br * 16 + cc) * 8 + (e - 5)];
        else v = l2_b[br * 16 + cc];
        swB[i] = v;
    }
    if (tid < 64) sbase[tid] = base_w[tid];
    if (tid < 16) { sbnS[tid] = bn_scale[tid]; sbnB[tid] = bn_bias[tid]; sfw[tid] = final_w[tid]; }

    int tx = tid & 31, ty = tid >> 5;     // ty 0..7; px (ty,tx) and (ty+8,tx)
    int x0 = blockIdx.x * 32, y0 = blockIdx.y * 16;
    int b = blockIdx.z;
    float fb = __ldg(final_b);
    float acc0 = fb, acc1 = fb;

    const float* s1 = g_xs + (size_t)((0 * BATCH + b) * 16) * HW;
    const float* s3 = g_xs + (size_t)((1 * BATCH + b) * 16) * HW;
    const float* s5 = g_xs + (size_t)((2 * BATCH + b) * 16) * HW;
    const float* s7 = g_xs + (size_t)((3 * BATCH + b) * 16) * HW;

    float r1[3], r3[4], r5[5], r7[6];
    m_prefetch<1, 3>(r1, s1, y0, x0, tid);
    m_prefetch<3, 4>(r3, s3, y0, x0, tid);
    m_prefetch<5, 5>(r5, s5, y0, x0, tid);
    m_prefetch<7, 6>(r7, s7, y0, x0, tid);

#pragma unroll 1
    for (int c = 0; c < 16; c++) {
        __syncthreads();
        m_commit<1, 3>(r1, sxt + 0,    tid);
        m_commit<3, 4>(r3, sxt + 612,  tid);
        m_commit<5, 5>(r5, sxt + 1448, tid);
        m_commit<7, 6>(r7, sxt + 2540, tid);
        __syncthreads();
        if (c < 15) {
            size_t off = (size_t)(c + 1) * HW;
            m_prefetch<1, 3>(r1, s1 + off, y0, x0, tid);
            m_prefetch<3, 4>(r3, s3 + off, y0, x0, tid);
            m_prefetch<5, 5>(r5, s5 + off, y0, x0, tid);
            m_prefetch<7, 6>(r7, s7 + off, y0, x0, tid);
        }

        float bva[4], bvb[4];
        branch_val_2y<1, 34>(sxt + 0,    ty, tx, swB + (0 * 16 + c) * 14, bva[0], bvb[0]);
        branch_val_2y<3, 38>(sxt + 612,  ty, tx, swB + (1 * 16 + c) * 14, bva[1], bvb[1]);
        branch_val_2y<5, 42>(sxt + 1448, ty, tx, swB + (2 * 16 + c) * 14, bva[2], bvb[2]);
        branch_val_2y<7, 46>(sxt + 2540, ty, tx, swB + (3 * 16 + c) * 14, bva[3], bvb[3]);

        // sort4 ascending per px
        ce(bva[0], bva[1]); ce(bva[2], bva[3]); ce(bva[0], bva[2]); ce(bva[1], bva[3]); ce(bva[1], bva[2]);
        ce(bvb[0], bvb[1]); ce(bvb[2], bvb[3]); ce(bvb[0], bvb[2]); ce(bvb[1], bvb[3]); ce(bvb[1], bvb[2]);

        float y0v = bva[0] * sbase[c * 4 + 0];
        y0v = fmaf(bva[1], sbase[c * 4 + 1], y0v);
        y0v = fmaf(bva[2], sbase[c * 4 + 2], y0v);
        y0v = fmaf(bva[3], sbase[c * 4 + 3], y0v);
        float y1v = bvb[0] * sbase[c * 4 + 0];
        y1v = fmaf(bvb[1], sbase[c * 4 + 1], y1v);
        y1v = fmaf(bvb[2], sbase[c * 4 + 2], y1v);
        y1v = fmaf(bvb[3], sbase[c * 4 + 3], y1v);
        float t0 = fmaf(y0v, sbnS[c], sbnB[c]);
        float t1 = fmaf(y1v, sbnS[c], sbnB[c]);
        float si0 = __fdividef(t0, 1.f + __expf(-t0));
        float si1 = __fdividef(t1, 1.f + __expf(-t1));
        acc0 = fmaf(si0, sfw[c], acc0);
        acc1 = fmaf(si1, sfw[c], acc1);
    }
    size_t obase = (size_t)b * HW + (size_t)y0 * 256 + x0 + tx;
    out[obase + (size_t)ty * 256]       = __fdividef(1.f, 1.f + __expf(-acc0));
    out[obase + (size_t)(ty + 8) * 256] = __fdividef(1.f, 1.f + __expf(-acc1));
}

// ---------------------------------------------------------------------------
extern "C" void kernel_launch(void* const* d_in, const int* in_sizes, int n_in,
                              void* d_out, int out_size) {
    (void)in_sizes; (void)n_in; (void)out_size;
    const ull* cen = (const ull*)d_in[0];
    // d_in[1] = mas (unused by the reference computation)
    const float* in_w = (const float*)d_in[2];
    const float* in_b = (const float*)d_in[3];

    k_inconv<<<1024, 256>>>(cen, in_w, in_b);

    dim3 g2(8, 16, 8);   // W/32, H/16, B
    k_dw<<<g2, 256>>>((const float*)d_in[4],  (const float*)d_in[5],
                      (const float*)d_in[6],  (const float*)d_in[7],
                      (const float*)d_in[8],  (const float*)d_in[9],
                      (const float*)d_in[10], (const float*)d_in[11]);

    dim3 g3(8, 16, 8);   // W/32, H/16, B
    k_main<<<g3, 256>>>((const float*)d_in[12], (const float*)d_in[13],
                        (const float*)d_in[14], (const float*)d_in[15],
                        (const float*)d_in[16], (const float*)d_in[17],
                        (const float*)d_in[18], (const float*)d_in[19],
                        (const float*)d_in[20], (float*)d_out);
}

// round 12
// speedup vs baseline: 1.3436x; 1.0113x over previous
#include <cuda_runtime.h>
#include <cuda_fp16.h>

#define HH 256
#define WW 256
#define BATCH 8
#define HW 65536

typedef unsigned long long ull;

// Scratch (allocation-free rule: __device__ globals)
__device__ float g_x[BATCH * 16 * HW];           // in_conv output  (33.5 MB)
__device__ __half g_xs[4 * BATCH * 16 * HW];     // dwconv outputs  (67 MB, fp16)

// ---------------- packed f32x2 helpers (sm_100+) ----------------
__device__ __forceinline__ ull pk2(float lo, float hi) {
    ull r;
    asm("mov.b64 %0, {%1, %2};" : "=l"(r) : "r"(__float_as_uint(lo)), "r"(__float_as_uint(hi)));
    return r;
}
__device__ __forceinline__ ull fma2(ull a, ull b, ull c) {
    ull d; asm("fma.rn.f32x2 %0, %1, %2, %3;" : "=l"(d) : "l"(a), "l"(b), "l"(c)); return d;
}

// ---------------------------------------------------------------------------
// K1: 1x1 in_conv 64 -> 16, packed f32x2 FFMA2 (2 px / thread)  [proven]
// ---------------------------------------------------------------------------
__global__ __launch_bounds__(256, 3) void k_inconv(const ull* __restrict__ cen2,
                                                   const float* __restrict__ w,
                                                   const float* __restrict__ bias) {
    __shared__ ull sw[1024];     // {w,w} packed
    __shared__ ull sb[16];
    for (int i = threadIdx.x; i < 1024; i += 256) { float v = w[i]; sw[i] = pk2(v, v); }
    if (threadIdx.x < 16) { float v = bias[threadIdx.x]; sb[threadIdx.x] = pk2(v, v); }
    __syncthreads();

    int idx = blockIdx.x * 256 + threadIdx.x;   // 0 .. 262143  (b, p2)
    int b = idx >> 15;
    int p2 = idx & 32767;
    const ull* cp = cen2 + (size_t)(b * 64) * 32768 + p2;

    ull acc[16];
#pragma unroll
    for (int o = 0; o < 16; o++) acc[o] = sb[o];

#pragma unroll 8
    for (int i = 0; i < 64; i++) {
        ull v = __ldg(cp + (size_t)i * 32768);
#pragma unroll
        for (int o = 0; o < 16; o++) acc[o] = fma2(v, sw[o * 64 + i], acc[o]);
    }
    ull* xp = reinterpret_cast<ull*>(g_x) + (size_t)(b * 16) * 32768 + p2;
#pragma unroll
    for (int o = 0; o < 16; o++) xp[(size_t)o * 32768] = acc[o];
}

// ---------------------------------------------------------------------------
// K2: all 4 depthwise convs (s = 1,3,5,7), tile 32x16, 2 px per thread,
//     register-prefetch pipeline over channels.  Outputs fp16.
// ---------------------------------------------------------------------------
template <int S>
__device__ __forceinline__ void dw2(const float* __restrict__ sx, int ty, int c0,
                                    const float* __restrict__ wk, float bias,
                                    float& o0, float& o1) {
    constexpr int P = S / 2;
    float a0 = bias, a1 = bias;
#pragma unroll
    for (int kh = 0; kh < S; kh++) {
        const float* row = sx + (ty + 3 - P + kh) * 39 + (c0 + 3 - P);
        float v[S + 1];
#pragma unroll
        for (int j = 0; j <= S; j++) v[j] = row[j];
#pragma unroll
        for (int kw = 0; kw < S; kw++) {
            float wv = wk[kh * S + kw];
            a0 = fmaf(wv, v[kw], a0);
            a1 = fmaf(wv, v[kw + 1], a1);
        }
    }
    o0 = a0; o1 = a1;
}

__device__ __forceinline__ void dw_prefetch(float r[4], const float* __restrict__ src,
                                            int y0, int x0, int tid) {
#pragma unroll
    for (int j = 0; j < 4; j++) {
        int i = tid + j * 256;
        float v = 0.f;
        if (i < 836) {
            int rr = i / 38, cl = i % 38;
            int gy = y0 - 3 + rr, gx = x0 - 3 + cl;
            if ((unsigned)gy < 256u && (unsigned)gx < 256u)
                v = __ldg(src + gy * 256 + gx);
        }
        r[j] = v;
    }
}

__device__ __forceinline__ void dw_commit(const float r[4], float* __restrict__ sxt,
                                          int tid) {
#pragma unroll
    for (int j = 0; j < 4; j++) {
        int i = tid + j * 256;
        if (i < 836) sxt[(i / 38) * 39 + (i % 38)] = r[j];
    }
}

__global__ __launch_bounds__(256) void k_dw(
    const float* __restrict__ w1, const float* __restrict__ b1,
    const float* __restrict__ w3, const float* __restrict__ b3,
    const float* __restrict__ w5, const float* __restrict__ b5,
    const float* __restrict__ w7, const float* __restrict__ b7) {
    __shared__ float sdw[16 * 84];
    __shared__ float sdb[64];
    __shared__ float sxt[22 * 39];

    int tid = threadIdx.x;
    for (int i = tid; i < 16;  i += 256) sdw[i * 84] = w1[i];
    for (int i = tid; i < 144; i += 256) sdw[(i / 9)  * 84 + 1  + (i % 9)]  = w3[i];
    for (int i = tid; i < 400; i += 256) sdw[(i / 25) * 84 + 10 + (i % 25)] = w5[i];
    for (int i = tid; i < 784; i += 256) sdw[(i / 49) * 84 + 35 + (i % 49)] = w7[i];
    if (tid < 16) {
        sdb[tid * 4 + 0] = b1[tid]; sdb[tid * 4 + 1] = b3[tid];
        sdb[tid * 4 + 2] = b5[tid]; sdb[tid * 4 + 3] = b7[tid];
    }

    int ty = tid >> 4;
    int c0 = (tid & 15) * 2;
    int y0 = blockIdx.y * 16, x0 = blockIdx.x * 32;
    int b = blockIdx.z;
    int h = y0 + ty, wc0 = x0 + c0;

    float rb[4];
    dw_prefetch(rb, g_x + (size_t)(b * 16 + 0) * HW, y0, x0, tid);

#pragma unroll 1
    for (int c = 0; c < 16; c++) {
        __syncthreads();
        dw_commit(rb, sxt, tid);
        __syncthreads();
        if (c < 15)
            dw_prefetch(rb, g_x + (size_t)(b * 16 + c + 1) * HW, y0, x0, tid);

        const float* wcp = sdw + c * 84;
        size_t pix = (size_t)h * 256 + wc0;
        float o0, o1;
        dw2<1>(sxt, ty, c0, wcp + 0,  sdb[c * 4 + 0], o0, o1);
        *reinterpret_cast<__half2*>(g_xs + (size_t)((0 * BATCH + b) * 16 + c) * HW + pix) =
            __halves2half2(__float2half_rn(o0), __float2half_rn(o1));
        dw2<3>(sxt, ty, c0, wcp + 1,  sdb[c * 4 + 1], o0, o1);
        *reinterpret_cast<__half2*>(g_xs + (size_t)((1 * BATCH + b) * 16 + c) * HW + pix) =
            __halves2half2(__float2half_rn(o0), __float2half_rn(o1));
        dw2<5>(sxt, ty, c0, wcp + 10, sdb[c * 4 + 2], o0, o1);
        *reinterpret_cast<__half2*>(g_xs + (size_t)((2 * BATCH + b) * 16 + c) * HW + pix) =
            __halves2half2(__float2half_rn(o0), __float2half_rn(o1));
        dw2<7>(sxt, ty, c0, wcp + 35, sdb[c * 4 + 3], o0, o1);
        *reinterpret_cast<__half2*>(g_xs + (size_t)((3 * BATCH + b) * 16 + c) * HW + pix) =
            __halves2half2(__float2half_rn(o0), __float2half_rn(o1));
    }
}

// ---------------------------------------------------------------------------
// K3: fused tail, tile 32x16, 512 threads, scalar fp32 math, channel prefetch.
// Stages fp16 gmem -> fp32 smem.
// ---------------------------------------------------------------------------
__device__ __forceinline__ void ce(float& a, float& b) {
    float lo = fminf(a, b);
    float hi = fmaxf(a, b);
    a = lo; b = hi;
}

template <int S, int C>
__device__ __forceinline__ float branch_val(const float* __restrict__ sx, int ty,
                                            int tx, const float* __restrict__ wB) {
    const float* ctr = sx + (ty + S) * C + (tx + S);
    float xc = ctr[0];
    float T[8];
    T[0] = xc - ctr[-S * C - S];
    T[1] = xc - ctr[-S * C];
    T[2] = xc - ctr[-S * C + S];
    T[3] = xc - ctr[S];
    T[4] = xc - ctr[S * C + S];
    T[5] = xc - ctr[S * C];
    T[6] = xc - ctr[S * C - S];
    T[7] = xc - ctr[-S];
    float Sv[4];
#pragma unroll
    for (int k = 0; k < 4; k++) Sv[k] = T[k] + T[k + 4];

    float w10 = wB[0], w11 = wB[1], w12 = wB[2], w13x2 = wB[3], b1 = wB[4];
    float base[4];
#pragma unroll
    for (int j = 0; j < 4; j++) {
        float o = fmaf(w10, Sv[(j + 1) & 3], b1);
        o = fmaf(w11, Sv[(j + 3) & 3], o);
        base[j] = fmaf(w12, Sv[(j + 2) & 3], o);
    }
    float v[8];
#pragma unroll
    for (int k = 0; k < 8; k++)
        v[k] = fmaf(w13x2, T[(k + 4) & 7], base[k & 3]) * T[k];  // wB[3] pre-doubled

    // Batcher odd-even mergesort, 8 elems, 19 CEs, ascending
    ce(v[0], v[1]); ce(v[2], v[3]); ce(v[0], v[2]); ce(v[1], v[3]); ce(v[1], v[2]);
    ce(v[4], v[5]); ce(v[6], v[7]); ce(v[4], v[6]); ce(v[5], v[7]); ce(v[5], v[6]);
    ce(v[0], v[4]); ce(v[1], v[5]); ce(v[2], v[6]); ce(v[3], v[7]);
    ce(v[2], v[4]); ce(v[3], v[5]);
    ce(v[1], v[2]); ce(v[3], v[4]); ce(v[5], v[6]);

    float r = wB[13];
#pragma unroll
    for (int j = 0; j < 8; j++) r = fmaf(v[j], wB[5 + j], r);
    return r;
}

template <int S, int NR>
__device__ __forceinline__ void m_prefetch(float r[NR], const __half* __restrict__ src,
                                           int y0, int x0, int tid) {
    constexpr int R = 16 + 2 * S, C = 32 + 2 * S;
#pragma unroll
    for (int j = 0; j < NR; j++) {
        int i = tid + j * 512;
        float v = 0.f;
        if (i < R * C) {
            int rr = i / C, cl = i % C;
            int gy = y0 - S + rr, gx = x0 - S + cl;
            if ((unsigned)gy < 256u && (unsigned)gx < 256u)
                v = __half2float(__ldg(src + gy * 256 + gx));
        }
        r[j] = v;
    }
}

template <int S, int NR>
__device__ __forceinline__ void m_commit(const float r[NR], float* __restrict__ dst,
                                         int tid) {
    constexpr int R = 16 + 2 * S, C = 32 + 2 * S;
#pragma unroll
    for (int j = 0; j < NR; j++) {
        int i = tid + j * 512;
        if (i < R * C) dst[i] = r[j];
    }
}

__global__ __launch_bounds__(512) void k_main(
    const float* __restrict__ l1_w, const float* __restrict__ l1_b,
    const float* __restrict__ l2_w, const float* __restrict__ l2_b,
    const float* __restrict__ base_w, const float* __restrict__ bn_scale,
    const float* __restrict__ bn_bias, const float* __restrict__ final_w,
    const float* __restrict__ final_b, float* __restrict__ out) {
    // Regions for 32x16 tile: S=1: 18x34=612 @0; S=3: 22x38=836 @612;
    // S=5: 26x42=1092 @1448; S=7: 30x46=1380 @2540; total 3920
    __shared__ float sxt[3920];
    __shared__ float swB[4 * 16 * 14];   // per branch/channel: w1[4],b1,w2[8],b2
    __shared__ float sbase[64];
    __shared__ float sbnS[16], sbnB[16], sfw[16];

    int tid = threadIdx.x;
    for (int i = tid; i < 896; i += 512) {
        int e = i % 14;
        int rest = i / 14;
        int cc = rest % 16, br = rest / 16;
        float v;
        if (e < 4) { v = l1_w[(br * 16 + cc) * 4 + e]; if (e == 3) v *= 2.f; }
        else if (e == 4) v = l1_b[br * 16 + cc];
        else if (e < 13) v = l2_w[(br * 16 + cc) * 8 + (e - 5)];
        else v = l2_b[br * 16 + cc];
        swB[i] = v;
    }
    if (tid < 64) sbase[tid] = base_w[tid];
    if (tid < 16) { sbnS[tid] = bn_scale[tid]; sbnB[tid] = bn_bias[tid]; sfw[tid] = final_w[tid]; }

    int tx = tid & 31, ty = tid >> 5;     // ty 0..15
    int x0 = blockIdx.x * 32, y0 = blockIdx.y * 16;
    int b = blockIdx.z;
    float acc = __ldg(final_b);

    const __half* s1 = g_xs + (size_t)((0 * BATCH + b) * 16) * HW;
    const __half* s3 = g_xs + (size_t)((1 * BATCH + b) * 16) * HW;
    const __half* s5 = g_xs + (size_t)((2 * BATCH + b) * 16) * HW;
    const __half* s7 = g_xs + (size_t)((3 * BATCH + b) * 16) * HW;

    float r1[2], r3[2], r5[3], r7[3];
    m_prefetch<1, 2>(r1, s1, y0, x0, tid);
    m_prefetch<3, 2>(r3, s3, y0, x0, tid);
    m_prefetch<5, 3>(r5, s5, y0, x0, tid);
    m_prefetch<7, 3>(r7, s7, y0, x0, tid);

#pragma unroll 1
    for (int c = 0; c < 16; c++) {
        __syncthreads();
        m_commit<1, 2>(r1, sxt + 0,    tid);
        m_commit<3, 2>(r3, sxt + 612,  tid);
        m_commit<5, 3>(r5, sxt + 1448, tid);
        m_commit<7, 3>(r7, sxt + 2540, tid);
        __syncthreads();
        if (c < 15) {
            size_t off = (size_t)(c + 1) * HW;
            m_prefetch<1, 2>(r1, s1 + off, y0, x0, tid);
            m_prefetch<3, 2>(r3, s3 + off, y0, x0, tid);
            m_prefetch<5, 3>(r5, s5 + off, y0, x0, tid);
            m_prefetch<7, 3>(r7, s7 + off, y0, x0, tid);
        }

        float bv0 = branch_val<1, 34>(sxt + 0,    ty, tx, swB + (0 * 16 + c) * 14);
        float bv1 = branch_val<3, 38>(sxt + 612,  ty, tx, swB + (1 * 16 + c) * 14);
        float bv2 = branch_val<5, 42>(sxt + 1448, ty, tx, swB + (2 * 16 + c) * 14);
        float bv3 = branch_val<7, 46>(sxt + 2540, ty, tx, swB + (3 * 16 + c) * 14);

        // sort4 ascending
        ce(bv0, bv1); ce(bv2, bv3); ce(bv0, bv2); ce(bv1, bv3); ce(bv1, bv2);

        float y = bv0 * sbase[c * 4 + 0];
        y = fmaf(bv1, sbase[c * 4 + 1], y);
        y = fmaf(bv2, sbase[c * 4 + 2], y);
        y = fmaf(bv3, sbase[c * 4 + 3], y);
        float t = fmaf(y, sbnS[c], sbnB[c]);
        float si = __fdividef(t, 1.f + __expf(-t));          // SiLU (fast)
        acc = fmaf(si, sfw[c], acc);
    }
    out[(size_t)b * HW + (size_t)(y0 + ty) * 256 + (x0 + tx)] =
        __fdividef(1.f, 1.f + __expf(-acc));
}

// ---------------------------------------------------------------------------
extern "C" void kernel_launch(void* const* d_in, const int* in_sizes, int n_in,
                              void* d_out, int out_size) {
    (void)in_sizes; (void)n_in; (void)out_size;
    const ull* cen = (const ull*)d_in[0];
    // d_in[1] = mas (unused by the reference computation)
    const float* in_w = (const float*)d_in[2];
    const float* in_b = (const float*)d_in[3];

    k_inconv<<<1024, 256>>>(cen, in_w, in_b);

    dim3 g2(8, 16, 8);   // W/32, H/16, B
    k_dw<<<g2, 256>>>((const float*)d_in[4],  (const float*)d_in[5],
                      (const float*)d_in[6],  (const float*)d_in[7],
                      (const float*)d_in[8],  (const float*)d_in[9],
                      (const float*)d_in[10], (const float*)d_in[11]);

    dim3 g3(8, 16, 8);   // W/32, H/16, B
    k_main<<<g3, 512>>>((const float*)d_in[12], (const float*)d_in[13],
                        (const float*)d_in[14], (const float*)d_in[15],
                        (const float*)d_in[16], (const float*)d_in[17],
                        (const float*)d_in[18], (const float*)d_in[19],
                        (const float*)d_in[20], (float*)d_out);
}

// round 13
// speedup vs baseline: 1.3906x; 1.0350x over previous
#include <cuda_runtime.h>
#include <cuda_fp16.h>

#define HH 256
#define WW 256
#define BATCH 8
#define HW 65536

typedef unsigned long long ull;

// Scratch (allocation-free rule: __device__ globals)
__device__ float g_x[BATCH * 16 * HW];           // in_conv output  (33.5 MB)
__device__ __half g_xs[4 * BATCH * 16 * HW];     // dwconv outputs  (67 MB, fp16)

// ---------------- packed f32x2 helpers (sm_100+) ----------------
__device__ __forceinline__ ull pk2(float lo, float hi) {
    ull r;
    asm("mov.b64 %0, {%1, %2};" : "=l"(r) : "r"(__float_as_uint(lo)), "r"(__float_as_uint(hi)));
    return r;
}
__device__ __forceinline__ ull fma2(ull a, ull b, ull c) {
    ull d; asm("fma.rn.f32x2 %0, %1, %2, %3;" : "=l"(d) : "l"(a), "l"(b), "l"(c)); return d;
}

// ---------------------------------------------------------------------------
// K1: 1x1 in_conv 64 -> 16, packed f32x2 FFMA2 (2 px / thread)  [proven]
// ---------------------------------------------------------------------------
__global__ __launch_bounds__(256, 3) void k_inconv(const ull* __restrict__ cen2,
                                                   const float* __restrict__ w,
                                                   const float* __restrict__ bias) {
    __shared__ ull sw[1024];     // {w,w} packed
    __shared__ ull sb[16];
    for (int i = threadIdx.x; i < 1024; i += 256) { float v = w[i]; sw[i] = pk2(v, v); }
    if (threadIdx.x < 16) { float v = bias[threadIdx.x]; sb[threadIdx.x] = pk2(v, v); }
    __syncthreads();

    int idx = blockIdx.x * 256 + threadIdx.x;   // 0 .. 262143  (b, p2)
    int b = idx >> 15;
    int p2 = idx & 32767;
    const ull* cp = cen2 + (size_t)(b * 64) * 32768 + p2;

    ull acc[16];
#pragma unroll
    for (int o = 0; o < 16; o++) acc[o] = sb[o];

#pragma unroll 8
    for (int i = 0; i < 64; i++) {
        ull v = __ldg(cp + (size_t)i * 32768);
#pragma unroll
        for (int o = 0; o < 16; o++) acc[o] = fma2(v, sw[o * 64 + i], acc[o]);
    }
    ull* xp = reinterpret_cast<ull*>(g_x) + (size_t)(b * 16) * 32768 + p2;
#pragma unroll
    for (int o = 0; o < 16; o++) xp[(size_t)o * 32768] = acc[o];
}

// ---------------------------------------------------------------------------
// K2 (channel-parallel): one block = one (b, c), tile 32x32, 256 threads,
// 4-px x-run per thread for all 4 kernel sizes, ONE barrier, fp16 outputs.
// ---------------------------------------------------------------------------
template <int S>
__device__ __forceinline__ void dwrun4(const float* __restrict__ st, int ty, int xr,
                                       const float* __restrict__ wk, float bias,
                                       float o[4]) {
    constexpr int P = S / 2;
    o[0] = bias; o[1] = bias; o[2] = bias; o[3] = bias;
#pragma unroll
    for (int kh = 0; kh < S; kh++) {
        const float* row = st + (ty + 3 - P + kh) * 39 + (xr + 3 - P);
        float v[S + 3];
#pragma unroll
        for (int j = 0; j < S + 3; j++) v[j] = row[j];
#pragma unroll
        for (int kw = 0; kw < S; kw++) {
            float wv = wk[kh * S + kw];
            o[0] = fmaf(wv, v[kw + 0], o[0]);
            o[1] = fmaf(wv, v[kw + 1], o[1]);
            o[2] = fmaf(wv, v[kw + 2], o[2]);
            o[3] = fmaf(wv, v[kw + 3], o[3]);
        }
    }
}

__global__ __launch_bounds__(256) void k_dw(
    const float* __restrict__ w1, const float* __restrict__ b1,
    const float* __restrict__ w3, const float* __restrict__ b3,
    const float* __restrict__ w5, const float* __restrict__ b5,
    const float* __restrict__ w7, const float* __restrict__ b7) {
    __shared__ float st[38 * 39];    // 32x32 tile + halo 3, stride 39
    __shared__ float sdw[84];        // this channel's weights: w1@0,w3@1,w5@10,w7@35
    __shared__ float sdb[4];

    int tid = threadIdx.x;
    int bc = blockIdx.z;             // b*16 + c
    int b = bc >> 4, c = bc & 15;
    int y0 = blockIdx.y * 32, x0 = blockIdx.x * 32;

    // stage weights (84 floats) + biases
    if (tid == 0)  sdw[0] = __ldg(w1 + c);
    else if (tid < 10)  sdw[tid]      = __ldg(w3 + c * 9  + tid - 1);
    else if (tid < 35)  sdw[tid]      = __ldg(w5 + c * 25 + tid - 10);
    else if (tid < 84)  sdw[tid]      = __ldg(w7 + c * 49 + tid - 35);
    else if (tid < 88) {
        const float* bp[4] = {b1, b3, b5, b7};
        sdb[tid - 84] = __ldg(bp[tid - 84] + c);
    }

    // stage 38x38 halo tile
    const float* src = g_x + (size_t)(b * 16 + c) * HW;
#pragma unroll
    for (int j = 0; j < 6; j++) {
        int i = tid + j * 256;
        if (i < 38 * 38) {
            int r = i / 38, cl = i % 38;
            int gy = y0 - 3 + r, gx = x0 - 3 + cl;
            float v = 0.f;
            if ((unsigned)gy < 256u && (unsigned)gx < 256u)
                v = __ldg(src + gy * 256 + gx);
            st[r * 39 + cl] = v;
        }
    }
    __syncthreads();

    int ty = tid >> 3;               // 0..31
    int xr = (tid & 7) * 4;          // 0,4,..,28
    size_t pix = (size_t)((b * 16 + c)) * HW + (size_t)(y0 + ty) * 256 + (x0 + xr);

    float o[4];
    dwrun4<1>(st, ty, xr, sdw + 0, sdb[0], o);
    {
        __half2* dst = reinterpret_cast<__half2*>(g_xs + (size_t)0 * BATCH * 16 * HW + pix);
        dst[0] = __halves2half2(__float2half_rn(o[0]), __float2half_rn(o[1]));
        dst[1] = __halves2half2(__float2half_rn(o[2]), __float2half_rn(o[3]));
    }
    dwrun4<3>(st, ty, xr, sdw + 1, sdb[1], o);
    {
        __half2* dst = reinterpret_cast<__half2*>(g_xs + (size_t)1 * BATCH * 16 * HW + pix);
        dst[0] = __halves2half2(__float2half_rn(o[0]), __float2half_rn(o[1]));
        dst[1] = __halves2half2(__float2half_rn(o[2]), __float2half_rn(o[3]));
    }
    dwrun4<5>(st, ty, xr, sdw + 10, sdb[2], o);
    {
        __half2* dst = reinterpret_cast<__half2*>(g_xs + (size_t)2 * BATCH * 16 * HW + pix);
        dst[0] = __halves2half2(__float2half_rn(o[0]), __float2half_rn(o[1]));
        dst[1] = __halves2half2(__float2half_rn(o[2]), __float2half_rn(o[3]));
    }
    dwrun4<7>(st, ty, xr, sdw + 35, sdb[3], o);
    {
        __half2* dst = reinterpret_cast<__half2*>(g_xs + (size_t)3 * BATCH * 16 * HW + pix);
        dst[0] = __halves2half2(__float2half_rn(o[0]), __float2half_rn(o[1]));
        dst[1] = __halves2half2(__float2half_rn(o[2]), __float2half_rn(o[3]));
    }
}

// ---------------------------------------------------------------------------
// K3: fused tail, tile 32x16, 512 threads, scalar fp32 math, channel prefetch.
// Stages fp16 gmem -> fp32 smem.  [unchanged, proven]
// ---------------------------------------------------------------------------
__device__ __forceinline__ void ce(float& a, float& b) {
    float lo = fminf(a, b);
    float hi = fmaxf(a, b);
    a = lo; b = hi;
}

template <int S, int C>
__device__ __forceinline__ float branch_val(const float* __restrict__ sx, int ty,
                                            int tx, const float* __restrict__ wB) {
    const float* ctr = sx + (ty + S) * C + (tx + S);
    float xc = ctr[0];
    float T[8];
    T[0] = xc - ctr[-S * C - S];
    T[1] = xc - ctr[-S * C];
    T[2] = xc - ctr[-S * C + S];
    T[3] = xc - ctr[S];
    T[4] = xc - ctr[S * C + S];
    T[5] = xc - ctr[S * C];
    T[6] = xc - ctr[S * C - S];
    T[7] = xc - ctr[-S];
    float Sv[4];
#pragma unroll
    for (int k = 0; k < 4; k++) Sv[k] = T[k] + T[k + 4];

    float w10 = wB[0], w11 = wB[1], w12 = wB[2], w13x2 = wB[3], b1 = wB[4];
    float base[4];
#pragma unroll
    for (int j = 0; j < 4; j++) {
        float o = fmaf(w10, Sv[(j + 1) & 3], b1);
        o = fmaf(w11, Sv[(j + 3) & 3], o);
        base[j] = fmaf(w12, Sv[(j + 2) & 3], o);
    }
    float v[8];
#pragma unroll
    for (int k = 0; k < 8; k++)
        v[k] = fmaf(w13x2, T[(k + 4) & 7], base[k & 3]) * T[k];  // wB[3] pre-doubled

    // Batcher odd-even mergesort, 8 elems, 19 CEs, ascending
    ce(v[0], v[1]); ce(v[2], v[3]); ce(v[0], v[2]); ce(v[1], v[3]); ce(v[1], v[2]);
    ce(v[4], v[5]); ce(v[6], v[7]); ce(v[4], v[6]); ce(v[5], v[7]); ce(v[5], v[6]);
    ce(v[0], v[4]); ce(v[1], v[5]); ce(v[2], v[6]); ce(v[3], v[7]);
    ce(v[2], v[4]); ce(v[3], v[5]);
    ce(v[1], v[2]); ce(v[3], v[4]); ce(v[5], v[6]);

    float r = wB[13];
#pragma unroll
    for (int j = 0; j < 8; j++) r = fmaf(v[j], wB[5 + j], r);
    return r;
}

template <int S, int NR>
__device__ __forceinline__ void m_prefetch(float r[NR], const __half* __restrict__ src,
                                           int y0, int x0, int tid) {
    constexpr int R = 16 + 2 * S, C = 32 + 2 * S;
#pragma unroll
    for (int j = 0; j < NR; j++) {
        int i = tid + j * 512;
        float v = 0.f;
        if (i < R * C) {
            int rr = i / C, cl = i % C;
            int gy = y0 - S + rr, gx = x0 - S + cl;
            if ((unsigned)gy < 256u && (unsigned)gx < 256u)
                v = __half2float(__ldg(src + gy * 256 + gx));
        }
        r[j] = v;
    }
}

template <int S, int NR>
__device__ __forceinline__ void m_commit(const float r[NR], float* __restrict__ dst,
                                         int tid) {
    constexpr int R = 16 + 2 * S, C = 32 + 2 * S;
#pragma unroll
    for (int j = 0; j < NR; j++) {
        int i = tid + j * 512;
        if (i < R * C) dst[i] = r[j];
    }
}

__global__ __launch_bounds__(512) void k_main(
    const float* __restrict__ l1_w, const float* __restrict__ l1_b,
    const float* __restrict__ l2_w, const float* __restrict__ l2_b,
    const float* __restrict__ base_w, const float* __restrict__ bn_scale,
    const float* __restrict__ bn_bias, const float* __restrict__ final_w,
    const float* __restrict__ final_b, float* __restrict__ out) {
    // Regions for 32x16 tile: S=1: 18x34=612 @0; S=3: 22x38=836 @612;
    // S=5: 26x42=1092 @1448; S=7: 30x46=1380 @2540; total 3920
    __shared__ float sxt[3920];
    __shared__ float swB[4 * 16 * 14];   // per branch/channel: w1[4],b1,w2[8],b2
    __shared__ float sbase[64];
    __shared__ float sbnS[16], sbnB[16], sfw[16];

    int tid = threadIdx.x;
    for (int i = tid; i < 896; i += 512) {
        int e = i % 14;
        int rest = i / 14;
        int cc = rest % 16, br = rest / 16;
        float v;
        if (e < 4) { v = l1_w[(br * 16 + cc) * 4 + e]; if (e == 3) v *= 2.f; }
        else if (e == 4) v = l1_b[br * 16 + cc];
        else if (e < 13) v = l2_w[(br * 16 + cc) * 8 + (e - 5)];
        else v = l2_b[br * 16 + cc];
        swB[i] = v;
    }
    if (tid < 64) sbase[tid] = base_w[tid];
    if (tid < 16) { sbnS[tid] = bn_scale[tid]; sbnB[tid] = bn_bias[tid]; sfw[tid] = final_w[tid]; }

    int tx = tid & 31, ty = tid >> 5;     // ty 0..15
    int x0 = blockIdx.x * 32, y0 = blockIdx.y * 16;
    int b = blockIdx.z;
    float acc = __ldg(final_b);

    const __half* s1 = g_xs + (size_t)((0 * BATCH + b) * 16) * HW;
    const __half* s3 = g_xs + (size_t)((1 * BATCH + b) * 16) * HW;
    const __half* s5 = g_xs + (size_t)((2 * BATCH + b) * 16) * HW;
    const __half* s7 = g_xs + (size_t)((3 * BATCH + b) * 16) * HW;

    float r1[2], r3[2], r5[3], r7[3];
    m_prefetch<1, 2>(r1, s1, y0, x0, tid);
    m_prefetch<3, 2>(r3, s3, y0, x0, tid);
    m_prefetch<5, 3>(r5, s5, y0, x0, tid);
    m_prefetch<7, 3>(r7, s7, y0, x0, tid);

#pragma unroll 1
    for (int c = 0; c < 16; c++) {
        __syncthreads();
        m_commit<1, 2>(r1, sxt + 0,    tid);
        m_commit<3, 2>(r3, sxt + 612,  tid);
        m_commit<5, 3>(r5, sxt + 1448, tid);
        m_commit<7, 3>(r7, sxt + 2540, tid);
        __syncthreads();
        if (c < 15) {
            size_t off = (size_t)(c + 1) * HW;
            m_prefetch<1, 2>(r1, s1 + off, y0, x0, tid);
            m_prefetch<3, 2>(r3, s3 + off, y0, x0, tid);
            m_prefetch<5, 3>(r5, s5 + off, y0, x0, tid);
            m_prefetch<7, 3>(r7, s7 + off, y0, x0, tid);
        }

        float bv0 = branch_val<1, 34>(sxt + 0,    ty, tx, swB + (0 * 16 + c) * 14);
        float bv1 = branch_val<3, 38>(sxt + 612,  ty, tx, swB + (1 * 16 + c) * 14);
        float bv2 = branch_val<5, 42>(sxt + 1448, ty, tx, swB + (2 * 16 + c) * 14);
        float bv3 = branch_val<7, 46>(sxt + 2540, ty, tx, swB + (3 * 16 + c) * 14);

        // sort4 ascending
        ce(bv0, bv1); ce(bv2, bv3); ce(bv0, bv2); ce(bv1, bv3); ce(bv1, bv2);

        float y = bv0 * sbase[c * 4 + 0];
        y = fmaf(bv1, sbase[c * 4 + 1], y);
        y = fmaf(bv2, sbase[c * 4 + 2], y);
        y = fmaf(bv3, sbase[c * 4 + 3], y);
        float t = fmaf(y, sbnS[c], sbnB[c]);
        float si = __fdividef(t, 1.f + __expf(-t));          // SiLU (fast)
        acc = fmaf(si, sfw[c], acc);
    }
    out[(size_t)b * HW + (size_t)(y0 + ty) * 256 + (x0 + tx)] =
        __fdividef(1.f, 1.f + __expf(-acc));
}

// ---------------------------------------------------------------------------
extern "C" void kernel_launch(void* const* d_in, const int* in_sizes, int n_in,
                              void* d_out, int out_size) {
    (void)in_sizes; (void)n_in; (void)out_size;
    const ull* cen = (const ull*)d_in[0];
    // d_in[1] = mas (unused by the reference computation)
    const float* in_w = (const float*)d_in[2];
    const float* in_b = (const float*)d_in[3];

    k_inconv<<<1024, 256>>>(cen, in_w, in_b);

    dim3 g2(8, 8, 128);   // W/32, H/32, B*C
    k_dw<<<g2, 256>>>((const float*)d_in[4],  (const float*)d_in[5],
                      (const float*)d_in[6],  (const float*)d_in[7],
                      (const float*)d_in[8],  (const float*)d_in[9],
                      (const float*)d_in[10], (const float*)d_in[11]);

    dim3 g3(8, 16, 8);   // W/32, H/16, B
    k_main<<<g3, 512>>>((const float*)d_in[12], (const float*)d_in[13],
                        (const float*)d_in[14], (const float*)d_in[15],
                        (const float*)d_in[16], (const float*)d_in[17],
                        (const float*)d_in[18], (const float*)d_in[19],
                        (const float*)d_in[20], (float*)d_out);
}